// round 2
// baseline (speedup 1.0000x reference)
#include <cuda_runtime.h>
#include <math_constants.h>

// Problem constants
#define NROWS   1024
#define REPD    256
#define NPIX    32768      // 8 * 64 * 64
#define LOG2E_F   1.4426950408889634f
#define LOG_2PI_F 1.8378770664093453f
#define EPS_F     1e-6f

__device__ __forceinline__ float ex2f(float x) {
    float y;
    asm("ex2.approx.ftz.f32 %0, %1;" : "=f"(y) : "f"(x));
    return y;
}

// numerically stable softplus (used only ~12x per block, accuracy-first)
__device__ __forceinline__ float softplusf(float x) {
    return fmaxf(x, 0.0f) + log1pf(expf(-fabsf(x)));
}

__global__ __launch_bounds__(256) void mvn_profile_kernel(
    const float* __restrict__ rep,     // [1024,256]
    const float* __restrict__ meanW,   // [3,256]
    const float* __restrict__ meanb,   // [3]
    const float* __restrict__ scaleW,  // [6,256]
    const float* __restrict__ scaleb,  // [6]
    float* __restrict__ out)           // [1024,32768]
{
    __shared__ float red[8][9];
    __shared__ float dots[9];
    __shared__ float wm[8], wS[8];
    __shared__ float s_U, s_S;

    const int row  = blockIdx.x;
    const int t    = threadIdx.x;
    const int warp = t >> 5;
    const int lane = t & 31;

    // ---- Phase 1: 9 dot products (3 means + 6 raw scales) ----
    float r = rep[row * REPD + t];
    float p[9];
#pragma unroll
    for (int k = 0; k < 3; k++) p[k]     = r * meanW[k * REPD + t];
#pragma unroll
    for (int k = 0; k < 6; k++) p[3 + k] = r * scaleW[k * REPD + t];

#pragma unroll
    for (int k = 0; k < 9; k++) {
        float v = p[k];
#pragma unroll
        for (int o = 16; o; o >>= 1) v += __shfl_xor_sync(0xffffffffu, v, o);
        if (lane == 0) red[warp][k] = v;
    }
    __syncthreads();
    if (t < 9) {
        float s = (t < 3) ? meanb[t] : scaleb[t - 3];
#pragma unroll
        for (int w = 0; w < 8; w++) s += red[w][t];
        dots[t] = s;
    }
    __syncthreads();

    // ---- Phase 2: derive quadratic-form coefficients (redundant per thread) ----
    const float mx = dots[0], my = dots[1], mz = dots[2];
    const float s0 = softplusf(dots[3]) + EPS_F;
    const float s1 = softplusf(dots[4]) + EPS_F;
    const float s2 = softplusf(dots[5]) + EPS_F;
    const float s3 = softplusf(dots[6]) + EPS_F;
    const float s4 = softplusf(dots[7]) + EPS_F;
    const float s5 = softplusf(dots[8]) + EPS_F;

    const float L00 = softplusf(s0);
    const float L10 = s1;
    const float L11 = softplusf(s2);
    const float L20 = s3;
    const float L21 = s4;
    const float L22 = softplusf(s5);

    const float a = 1.0f / L00, b = 1.0f / L11, c = 1.0f / L22;
    // M = L^{-1} (lower triangular)
    const float m10 = -L10 * a * b;
    const float m21 = -L21 * b * c;
    const float m20 = -c * (L20 * a + L21 * m10);
    // Q = M^T M; maha = Qxx dx^2 + Qyy dy^2 + Qzz dz^2 + Qxy dx dy + Qxz dx dz + Qyz dy dz
    const float Qxx = a * a + m10 * m10 + m20 * m20;
    const float Qyy = b * b + m21 * m21;
    const float Qzz = c * c;
    const float Qxy = 2.0f * (m10 * b + m20 * m21);
    const float Qxz = 2.0f * (m20 * c);
    const float Qyz = 2.0f * (m21 * c);

    const float al  = -0.5f * LOG2E_F;   // fold -0.5 and base-2 conversion
    const float qxx = al * Qxx, qyy = al * Qyy, qzz = al * Qzz;
    const float qxy = al * Qxy, qxz = al * Qxz, qyz = al * Qyz;

    const float logdet = logf(L00) + logf(L11) + logf(L22);
    const float K = LOG2E_F * (-logdet - 1.5f * LOG_2PI_F);  // u = log2(e)*log_prob

    // x positions per thread are constant across all iterations:
    // pixel index p = 1024*i + 4*t  ->  x-index = 4*(t&15)+j, scanline = 16*i + (t>>4)
    const float x0  = 4.0f * (float)(t & 15) - 31.5f;
    const float dx0 = x0 - mx, dx1 = dx0 + 1.0f, dx2 = dx0 + 2.0f, dx3 = dx0 + 3.0f;
    const float h0 = qxx * dx0, h1 = qxx * dx1, h2 = qxx * dx2, h3 = qxx * dx3;
    const int rbase = t >> 4;

    // ---- Sweep A: online (flash-style) max + sum of exp2(u - m) ----
    float m = -CUDART_INF_F;
    float S = 0.0f;
#pragma unroll 4
    for (int i = 0; i < 32; i++) {
        const int   rowid = i * 16 + rbase;          // 0..511 scanlines
        const float dy = (float)(rowid & 63) - 31.5f - my;
        const float dz = (float)(rowid >> 6) - 3.5f  - mz;
        const float B0 = fmaf(qxy, dy, qxz * dz);
        const float C0 = fmaf(dy, fmaf(qyy, dy, qyz * dz), fmaf(qzz * dz, dz, K));
        const float u0 = fmaf(dx0, h0 + B0, C0);
        const float u1 = fmaf(dx1, h1 + B0, C0);
        const float u2 = fmaf(dx2, h2 + B0, C0);
        const float u3 = fmaf(dx3, h3 + B0, C0);
        const float m4 = fmaxf(fmaxf(u0, u1), fmaxf(u2, u3));
        if (m4 > m) { S *= ex2f(m - m4); m = m4; }   // rare rescale
        S += ex2f(u0 - m) + ex2f(u1 - m) + ex2f(u2 - m) + ex2f(u3 - m);
    }

    // warp-level combine of (m, S)
#pragma unroll
    for (int o = 16; o; o >>= 1) {
        const float om = __shfl_xor_sync(0xffffffffu, m, o);
        const float oS = __shfl_xor_sync(0xffffffffu, S, o);
        const float nm = fmaxf(m, om);
        S = S * ex2f(m - nm) + oS * ex2f(om - nm);
        m = nm;
    }
    if (lane == 0) { wm[warp] = m; wS[warp] = S; }
    __syncthreads();
    if (t == 0) {
        float M = wm[0], SS = wS[0];
#pragma unroll
        for (int w = 1; w < 8; w++) {
            const float nm = fmaxf(M, wm[w]);
            SS = SS * ex2f(M - nm) + wS[w] * ex2f(wm[w] - nm);
            M = nm;
        }
        s_U = M;
        s_S = SS;
    }
    __syncthreads();

    // final exponent offset: u - U - log2(sum + 1e-10)
    const float K2 = K - s_U - __log2f(s_S + 1e-10f);

    // ---- Sweep B: write normalized profile (streaming float4 stores) ----
    float4* __restrict__ out4 = (float4*)(out + (size_t)row * NPIX);
#pragma unroll 4
    for (int i = 0; i < 32; i++) {
        const int   rowid = i * 16 + rbase;
        const float dy = (float)(rowid & 63) - 31.5f - my;
        const float dz = (float)(rowid >> 6) - 3.5f  - mz;
        const float B0 = fmaf(qxy, dy, qxz * dz);
        const float C0 = fmaf(dy, fmaf(qyy, dy, qyz * dz), fmaf(qzz * dz, dz, K2));
        float4 v;
        v.x = ex2f(fmaf(dx0, h0 + B0, C0));
        v.y = ex2f(fmaf(dx1, h1 + B0, C0));
        v.z = ex2f(fmaf(dx2, h2 + B0, C0));
        v.w = ex2f(fmaf(dx3, h3 + B0, C0));
        __stcs(&out4[i * 256 + t], v);   // evict-first: output >> L2
    }
}

extern "C" void kernel_launch(void* const* d_in, const int* in_sizes, int n_in,
                              void* d_out, int out_size) {
    const float* rep    = (const float*)d_in[0];
    const float* meanW  = (const float*)d_in[1];
    const float* meanb  = (const float*)d_in[2];
    const float* scaleW = (const float*)d_in[3];
    const float* scaleb = (const float*)d_in[4];
    float* out = (float*)d_out;

    mvn_profile_kernel<<<NROWS, 256>>>(rep, meanW, meanb, scaleW, scaleb, out);
}